// round 15
// baseline (speedup 1.0000x reference)
#include <cuda_runtime.h>
#include <cuda_bf16.h>
#include <cuda_fp16.h>
#include <cstdint>

// Problem constants
#define D      64
#define K      1024
#define HW     4096        // 64*64
#define NROWS  131072      // 32*64*64
#define MT     128         // rows per block
#define NT     64          // codes per tile
#define NTILES 16
#define XPITCH 132         // padded pitch for xs
#define BS_U32 2048        // B tile size in u32 (8KB)
#define CAP    16          // candidate slots per row

// Output layout (concatenated, float32): quantized_out (b,c,h,w), loss (b,h,w,c), idx (b,h,w)
#define LOFF   8388608
#define IOFF   16777216

// Scratch (no cudaMalloc allowed)
__device__ uint32_t g_eB[(K / 8) * 4 * 32 * 2];   // bf16 B fragments (R11 layout)
__device__ float    g_e2[K];                      // ||e_k||^2 (exact fp32 chain)
__device__ int      g_e2max_bits;                 // max ||e||^2 as float bits
// approx distances, fp16, 16384 x 16B chunks per CTA-block of 128 rows:
// chunk c = nt*1024 + w*128 + nb*32 + t  holds rows {(w&3)*32+(t>>2)} +{0,8,16,24}
// x codes {nt*64 + (w>>2)*32 + nb*8 + (t&3)*2 +{0,1}}
__device__ uint4    g_v4[(size_t)NROWS * K / 8];  // 268MB

static __device__ __forceinline__ uint32_t bf2(float hi, float lo) {
    uint32_t r;
    asm("cvt.rn.satfinite.bf16x2.f32 %0, %1, %2;" : "=r"(r) : "f"(hi), "f"(lo));
    return r;
}
__device__ __forceinline__ void cp_async16(uint32_t saddr, const void* gaddr) {
    asm volatile("cp.async.cg.shared.global [%0], [%1], 16;" :: "r"(saddr), "l"(gaddr) : "memory");
}
__device__ __forceinline__ void cp_commit() {
    asm volatile("cp.async.commit_group;" ::: "memory");
}
__device__ __forceinline__ void mma_bf16(float& c0, float& c1, float& c2, float& c3,
                                         uint32_t a0, uint32_t a1, uint32_t a2, uint32_t a3,
                                         uint32_t b0, uint32_t b1) {
    asm("mma.sync.aligned.m16n8k16.row.col.f32.bf16.bf16.f32 "
        "{%0,%1,%2,%3},{%4,%5,%6,%7},{%8,%9},{%0,%1,%2,%3};"
        : "+f"(c0), "+f"(c1), "+f"(c2), "+f"(c3)
        : "r"(a0), "r"(a1), "r"(a2), "r"(a3), "r"(b0), "r"(b1));
}
__device__ __forceinline__ unsigned fenc(float f) {
    unsigned u = __float_as_uint(f);
    return (u & 0x80000000u) ? ~u : (u | 0x80000000u);
}
__device__ __forceinline__ float fdec(unsigned k) {
    unsigned u = (k & 0x80000000u) ? (k & 0x7FFFFFFFu) : ~k;
    return __uint_as_float(u);
}

// ---------------------------------------------------------------------------
// Prep: pack bf16 B fragments + exact e2 (sequential d chain) + e2max.
// ---------------------------------------------------------------------------
__global__ void vq_prep_kernel(const float* __restrict__ emb) {
    int tid = threadIdx.x;
    if (blockIdx.x < 64) {
        int gid  = blockIdx.x * 256 + tid;      // 0..16383
        int lane = gid & 31, kc = (gid >> 5) & 3, nb = gid >> 7;
        int n  = nb * 8 + (lane >> 2);
        int kb = kc * 16 + (lane & 3) * 2;
        const float* e = emb + n * D + kb;
        g_eB[gid * 2]     = bf2(e[1], e[0]);
        g_eB[gid * 2 + 1] = bf2(e[9], e[8]);
    } else {
        int k = (blockIdx.x - 64) * 256 + tid;  // blocks 64..67 -> k 0..1023
        float4 v[16];
        const float4* row = (const float4*)(emb + k * D);
#pragma unroll
        for (int i = 0; i < 16; ++i) v[i] = row[i];
        float s = 0.0f;
#pragma unroll
        for (int i = 0; i < 16; ++i) {          // sequential d = 0..63 (reference order)
            s = fmaf(v[i].x, v[i].x, s);
            s = fmaf(v[i].y, v[i].y, s);
            s = fmaf(v[i].z, v[i].z, s);
            s = fmaf(v[i].w, v[i].w, s);
        }
        g_e2[k] = s;
        atomicMax(&g_e2max_bits, __float_as_int(s));
    }
}

// ---------------------------------------------------------------------------
// Main: SINGLE bf16 MMA pass (R13 remap: 2 row-blocks x 4 n-blocks per warp),
// storing all approx distances as fp16; then a scan phase with the FINAL
// threshold collects candidates; exact fp32-chain recheck; R13 epilogue.
// ---------------------------------------------------------------------------
extern __shared__ float sm[];

__global__ __launch_bounds__(256, 3) void vq_main_kernel(
    const float* __restrict__ x,     // [b, c, h, w] fp32
    const float* __restrict__ emb,   // [K, D] fp32
    float* __restrict__ out)
{
    float*    xs = sm;                            // [64][XPITCH]
    uint32_t* Bs = (uint32_t*)(sm + D * XPITCH);  // [2][2048] double-buffered B tiles
    __shared__ float    e2sh[2][NT];
    __shared__ float    rs[MT];
    __shared__ float    thrS[MT];                 // final threshold (incl. fp16 storage slack)
    __shared__ __half   maxthr4h[MT];             // round-up max over the 4 rows of a chunk
    __shared__ unsigned rminU[MT];
    __shared__ int      ccount[MT];
    __shared__ int      cidx[MT * CAP];
    __shared__ int      idxRow[MT];

    const int tid = threadIdx.x;
    const int p0  = blockIdx.x * MT;
    const int b   = p0 >> 12;
    const int s0  = p0 & 4095;
    const float* xbase = x + (size_t)b * 64 * HW + s0;
    const size_t vbase = (size_t)blockIdx.x * 16384;   // chunks

    const uint32_t bs_u = (uint32_t)__cvta_generic_to_shared(Bs);
    const uint32_t e2_u = (uint32_t)__cvta_generic_to_shared(e2sh);

    if (tid < MT) { ccount[tid] = 0; rminU[tid] = 0xFFFFFFFFu; }

    // ---- prefetch B tile 0 + e2 tile 0 ----
    {
#pragma unroll
        for (int i = 0; i < 2; ++i) {
            int c = tid + i * 256;
            cp_async16(bs_u + (uint32_t)c * 16, g_eB + c * 4);
        }
        if (tid < 16) cp_async16(e2_u + (uint32_t)tid * 16, g_e2 + tid * 4);
        cp_commit();
    }

    // ---- load x tile (float4) ----
#pragma unroll
    for (int i = 0; i < 8; ++i) {
        int f = tid + i * 256;
        int d = f >> 5, mf = f & 31;
        float4 v = *(const float4*)(xbase + d * HW + mf * 4);
        *(float4*)(xs + d * XPITCH + mf * 4) = v;
    }
    __syncthreads();

    // ---- per-row ||x||^2 (sequential d, reference order) ----
    if (tid < MT) {
        float s = 0.0f;
#pragma unroll
        for (int d = 0; d < D; ++d) {
            float v = xs[d * XPITCH + tid];
            s = fmaf(v, v, s);
        }
        rs[tid] = s;
    }

    // ---- warp remap: 2 row-blocks x 4 n-blocks per warp (R13) ----
    const int t  = tid & 31, w = tid >> 5;
    const int wr = w & 3;
    const int wn = w >> 2;
    const int r0 = wr * 32 + (t >> 2);   // thread rows: r0, r0+8, r0+16, r0+24
    const int q  = (t & 3) * 2;

    uint32_t A[2][4][4];
#pragma unroll
    for (int blk = 0; blk < 2; ++blk) {
        int r = r0 + blk * 16;
#pragma unroll
        for (int kc = 0; kc < 4; ++kc) {
            int k = kc * 16 + q;
            A[blk][kc][0] = bf2(xs[(k + 1) * XPITCH + r],     xs[k * XPITCH + r]);
            A[blk][kc][1] = bf2(xs[(k + 1) * XPITCH + r + 8], xs[k * XPITCH + r + 8]);
            A[blk][kc][2] = bf2(xs[(k + 9) * XPITCH + r],     xs[(k + 8) * XPITCH + r]);
            A[blk][kc][3] = bf2(xs[(k + 9) * XPITCH + r + 8], xs[(k + 8) * XPITCH + r + 8]);
        }
    }

    float rbest[4] = { 3.4e38f, 3.4e38f, 3.4e38f, 3.4e38f };

    // ================= SINGLE PASS: MMA + store fp16 distances =================
    for (int nt = 0; nt < NTILES; ++nt) {
        const int buf = nt & 1;
        __syncthreads();
        if (nt < NTILES - 1) {
            const uint32_t* src = g_eB + (nt + 1) * BS_U32;
            uint32_t dst = bs_u + (uint32_t)(buf ^ 1) * 8192;
#pragma unroll
            for (int i = 0; i < 2; ++i) {
                int c = tid + i * 256;
                cp_async16(dst + (uint32_t)c * 16, src + c * 4);
            }
            if (tid < 16)
                cp_async16(e2_u + (uint32_t)((buf ^ 1) * NT + tid * 4) * 4,
                           g_e2 + (nt + 1) * NT + tid * 4);
            cp_commit();
            asm volatile("cp.async.wait_group 1;" ::: "memory");
        } else {
            asm volatile("cp.async.wait_group 0;" ::: "memory");
        }
        __syncthreads();

        const uint32_t* bp  = Bs + buf * BS_U32;
        const float*    e2p = e2sh[buf];
#pragma unroll
        for (int nb = 0; nb < 4; ++nb) {
            int nblk = wn * 4 + nb;
            float c00 = 0.f, c01 = 0.f, c02 = 0.f, c03 = 0.f;
            float c10 = 0.f, c11 = 0.f, c12 = 0.f, c13 = 0.f;
#pragma unroll
            for (int kc = 0; kc < 4; ++kc) {
                uint2 bb = *(const uint2*)(bp + ((nblk * 4 + kc) * 32 + t) * 2);
                mma_bf16(c00, c01, c02, c03, A[0][kc][0], A[0][kc][1], A[0][kc][2], A[0][kc][3], bb.x, bb.y);
                mma_bf16(c10, c11, c12, c13, A[1][kc][0], A[1][kc][1], A[1][kc][2], A[1][kc][3], bb.x, bb.y);
            }
            float2 e2v = *(const float2*)(e2p + nblk * 8 + q);
            float v00 = fmaf(c00, -2.f, e2v.x), v01 = fmaf(c01, -2.f, e2v.y);
            float v02 = fmaf(c02, -2.f, e2v.x), v03 = fmaf(c03, -2.f, e2v.y);
            float v10 = fmaf(c10, -2.f, e2v.x), v11 = fmaf(c11, -2.f, e2v.y);
            float v12 = fmaf(c12, -2.f, e2v.x), v13 = fmaf(c13, -2.f, e2v.y);
            rbest[0] = fminf(rbest[0], fminf(v00, v01));
            rbest[1] = fminf(rbest[1], fminf(v02, v03));
            rbest[2] = fminf(rbest[2], fminf(v10, v11));
            rbest[3] = fminf(rbest[3], fminf(v12, v13));
            // store fp16 chunk (coalesced 512B/warp)
            __half2 h0 = __floats2half2_rn(v00, v01);
            __half2 h1 = __floats2half2_rn(v02, v03);
            __half2 h2 = __floats2half2_rn(v10, v11);
            __half2 h3 = __floats2half2_rn(v12, v13);
            uint4 u;
            u.x = *reinterpret_cast<uint32_t*>(&h0);
            u.y = *reinterpret_cast<uint32_t*>(&h1);
            u.z = *reinterpret_cast<uint32_t*>(&h2);
            u.w = *reinterpret_cast<uint32_t*>(&h3);
            g_v4[vbase + (size_t)(nt * 1024 + w * 128 + nb * 32 + t)] = u;
        }
    }

    // ---- final per-row min + threshold ----
#pragma unroll
    for (int i = 0; i < 4; ++i) {
        rbest[i] = fminf(rbest[i], __shfl_xor_sync(0xffffffff, rbest[i], 1));
        rbest[i] = fminf(rbest[i], __shfl_xor_sync(0xffffffff, rbest[i], 2));
    }
    if ((t & 3) == 0) {
#pragma unroll
        for (int i = 0; i < 4; ++i)
            atomicMin(&rminU[r0 + i * 8], fenc(rbest[i]));
    }
    __syncthreads();
    if (tid < MT) {
        float mn   = fdec(rminU[tid]);
        float e2mx = __int_as_float(g_e2max_bits);
        float emax = sqrtf(e2mx);
        float srn  = sqrtf(rs[tid]);
        float m    = fmaxf(0.016f * srn * emax + 1e-4f, 5e-4f);       // bf16 MMA margin
        float serr = 4.8828e-4f * (2.f * srn * emax + e2mx) + 1e-6f;  // fp16 storage slack
        thrS[tid]  = mn + 2.f * m + serr;
    }
    __syncthreads();
    if (tid < MT) {
        int base = (tid & 96) | (tid & 7);   // valid r0 pattern; harmless elsewhere
        float mx = fmaxf(fmaxf(thrS[base], thrS[base + 8]),
                         fmaxf(thrS[base + 16], thrS[base + 24]));
        maxthr4h[tid] = __float2half_ru(mx);
    }
    __syncthreads();

    // ================= SCAN: collect candidates from stored fp16 =================
#pragma unroll 4
    for (int i = 0; i < 64; ++i) {
        int c = tid + i * 256;                      // chunk id 0..16383
        uint4 u = g_v4[vbase + c];
        int ct  = c & 31;
        int r0s = ((c >> 7) & 3) * 32 + (ct >> 2);  // (w&3)*32 + (t>>2)
        __half2 a = *reinterpret_cast<__half2*>(&u.x);
        __half2 bh = *reinterpret_cast<__half2*>(&u.y);
        __half2 ch = *reinterpret_cast<__half2*>(&u.z);
        __half2 dh = *reinterpret_cast<__half2*>(&u.w);
        __half2 m2 = __hmin2(__hmin2(a, bh), __hmin2(ch, dh));
        __half  m1 = __hmin(__low2half(m2), __high2half(m2));
        if (__hle(m1, maxthr4h[r0s])) {
            int n0 = (c >> 10) * 64 + ((c >> 9) & 1) * 32 + ((c >> 5) & 3) * 8 + (ct & 3) * 2;
            float2 f0 = __half22float2(a), f1 = __half22float2(bh);
            float2 f2 = __half22float2(ch), f3 = __half22float2(dh);
            float tr0 = thrS[r0s], tr1 = thrS[r0s + 8], tr2 = thrS[r0s + 16], tr3 = thrS[r0s + 24];
            if (f0.x <= tr0) { int sl = atomicAdd(&ccount[r0s], 1);      if (sl < CAP) cidx[r0s * CAP + sl] = n0; }
            if (f0.y <= tr0) { int sl = atomicAdd(&ccount[r0s], 1);      if (sl < CAP) cidx[r0s * CAP + sl] = n0 + 1; }
            if (f1.x <= tr1) { int sl = atomicAdd(&ccount[r0s + 8], 1);  if (sl < CAP) cidx[(r0s + 8) * CAP + sl] = n0; }
            if (f1.y <= tr1) { int sl = atomicAdd(&ccount[r0s + 8], 1);  if (sl < CAP) cidx[(r0s + 8) * CAP + sl] = n0 + 1; }
            if (f2.x <= tr2) { int sl = atomicAdd(&ccount[r0s + 16], 1); if (sl < CAP) cidx[(r0s + 16) * CAP + sl] = n0; }
            if (f2.y <= tr2) { int sl = atomicAdd(&ccount[r0s + 16], 1); if (sl < CAP) cidx[(r0s + 16) * CAP + sl] = n0 + 1; }
            if (f3.x <= tr3) { int sl = atomicAdd(&ccount[r0s + 24], 1); if (sl < CAP) cidx[(r0s + 24) * CAP + sl] = n0; }
            if (f3.y <= tr3) { int sl = atomicAdd(&ccount[r0s + 24], 1); if (sl < CAP) cidx[(r0s + 24) * CAP + sl] = n0 + 1; }
        }
    }

    // ============ EXACT phase: reference-rounded recheck, u64 lex-min ============
    __syncthreads();
    unsigned long long* dex = (unsigned long long*)Bs;   // 2048 u64 = 16KB scratch
#pragma unroll
    for (int i = 0; i < 8; ++i) {
        int slot = tid + i * 256;            // 0..2047
        int m = slot >> 4, sl = slot & 15;
        int cnt = ccount[m];
        unsigned long long best = ~0ULL;
        if (cnt <= CAP) {
            if (sl < cnt) {
                int n = cidx[m * CAP + sl];
                const float* ep = emb + n * D;
                float dot = 0.f;
#pragma unroll 8
                for (int d = 0; d < D; ++d) dot = fmaf(xs[d * XPITCH + m], ep[d], dot);
                float vv = fmaf(dot, -2.f, rs[m] + g_e2[n]);   // reference rounding
                best = ((unsigned long long)fenc(vv) << 32) | (unsigned)n;
            }
        } else {
            // overflow fallback (prob ~0): distributed exact scan, 64 codes/thread
            for (int n = sl; n < K; n += 16) {
                const float* ep = emb + n * D;
                float dot = 0.f;
#pragma unroll 8
                for (int d = 0; d < D; ++d) dot = fmaf(xs[d * XPITCH + m], ep[d], dot);
                float vv = fmaf(dot, -2.f, rs[m] + g_e2[n]);
                unsigned long long e = ((unsigned long long)fenc(vv) << 32) | (unsigned)n;
                if (e < best) best = e;
            }
        }
        dex[slot] = best;
    }
    __syncthreads();
    if (tid < MT) {
        unsigned long long bv = ~0ULL;
#pragma unroll
        for (int tt = 0; tt < 16; ++tt) {
            unsigned long long e = dex[tid * 16 + tt];
            if (e < bv) bv = e;
        }
        int bi = (int)(unsigned)(bv & 0xFFFFFFFFu);
        idxRow[tid] = bi;
        out[IOFF + p0 + tid] = (float)bi;
    }
    __syncthreads();

    // ---- loss (b,h,w,c) ----
#pragma unroll
    for (int i = 0; i < 32; ++i) {
        int idx = tid + i * 256;
        int m = idx >> 6, c = idx & 63;
        float xv = xs[c * XPITCH + m];
        float ev = emb[idxRow[m] * D + c];
        float df = ev - xv;
        float tt = df * df;
        out[LOFF + (size_t)(p0 + m) * 64 + c] = tt + 0.25f * tt;
    }

    // ---- quantized_out (b,c,h,w) ----
#pragma unroll
    for (int i = 0; i < 32; ++i) {
        int idx = tid + i * 256;
        int c = idx >> 7, m = idx & 127;
        float xv = xs[c * XPITCH + m];
        float ev = emb[idxRow[m] * D + c];
        out[(size_t)(b * 64 + c) * HW + s0 + m] = xv + (ev - xv);
    }
}

// ---------------------------------------------------------------------------
extern "C" void kernel_launch(void* const* d_in, const int* in_sizes, int n_in,
                              void* d_out, int out_size)
{
    const float* x_in = (const float*)d_in[0];   // inputs  [32,64,64,64]
    const float* emb  = (const float*)d_in[1];   // embedding [1024,64]
    float* out = (float*)d_out;

    static bool attr_set = false;
    size_t smem_bytes = (size_t)(D * XPITCH * 4 + 2 * 8192);
    if (!attr_set) {
        cudaFuncSetAttribute(vq_main_kernel,
                             cudaFuncAttributeMaxDynamicSharedMemorySize,
                             (int)smem_bytes);
        attr_set = true;
    }

    vq_prep_kernel<<<68, 256>>>(emb);
    vq_main_kernel<<<NROWS / MT, 256, smem_bytes>>>(x_in, emb, out);
}